// round 8
// baseline (speedup 1.0000x reference)
#include <cuda_runtime.h>
#include <cuda_bf16.h>
#include <stdint.h>

// Problem constants
#define T_TOK   65536          // B*S*N tokens
#define DIMF    512
#define NHEADS  8
#define DH      64
#define N_PER   256
#define BSCNT   256
#define SCALE_F 0.044194173824159216f   // 512^-0.5

// Scratch (device globals: allocation-free per harness rules)
__device__ float g_q[(size_t)T_TOK * DIMF];
__device__ __nv_bfloat16 g_kb[(size_t)T_TOK * DIMF];
__device__ __nv_bfloat16 g_vb[(size_t)T_TOK * DIMF];
__device__ float g_gk[BSCNT * NHEADS * DH];
__device__ __nv_bfloat16 g_xhi[(size_t)T_TOK * DIMF];
__device__ __nv_bfloat16 g_xlo[(size_t)T_TOK * DIMF];
__device__ __nv_bfloat16 g_whi[3 * DIMF * DIMF];
__device__ __nv_bfloat16 g_wlo[DIMF * DIMF];          // only Wq needs lo

// ---------------------------------------------------------------------------
// PTX helpers
// ---------------------------------------------------------------------------
__device__ __forceinline__ uint32_t smem_u32(const void* p) {
    uint32_t a;
    asm("{ .reg .u64 t; cvta.to.shared.u64 t, %1; cvt.u32.u64 %0, t; }" : "=r"(a) : "l"(p));
    return a;
}
#define CP16(s, g) asm volatile("cp.async.cg.shared.global [%0], [%1], 16;" :: "r"(s), "l"(g))
#define CP_COMMIT() asm volatile("cp.async.commit_group;")
#define CP_WAITG(n) asm volatile("cp.async.wait_group %0;" :: "n"(n))

#define LDSM4(r, a) \
    asm volatile("ldmatrix.sync.aligned.m8n8.x4.shared.b16 {%0,%1,%2,%3}, [%4];" \
        : "=r"((r)[0]), "=r"((r)[1]), "=r"((r)[2]), "=r"((r)[3]) : "r"(a))

#define MMA16816(d, a, b) \
    asm volatile("mma.sync.aligned.m16n8k16.row.col.f32.bf16.bf16.f32 " \
        "{%0,%1,%2,%3}, {%4,%5,%6,%7}, {%8,%9}, {%0,%1,%2,%3};" \
        : "+f"((d)[0]), "+f"((d)[1]), "+f"((d)[2]), "+f"((d)[3]) \
        : "r"((a)[0]), "r"((a)[1]), "r"((a)[2]), "r"((a)[3]), "r"((b)[0]), "r"((b)[1]))

// ---------------------------------------------------------------------------
// Kernel 0a: split x (fp32) -> hi/lo bf16
// ---------------------------------------------------------------------------
__global__ __launch_bounds__(256) void cvt_x(const float* __restrict__ x)
{
    size_t i = ((size_t)blockIdx.x * 256 + threadIdx.x) * 4;
    float4 v = *(const float4*)(x + i);
    __nv_bfloat16 h0 = __float2bfloat16_rn(v.x);
    __nv_bfloat16 h1 = __float2bfloat16_rn(v.y);
    __nv_bfloat16 h2 = __float2bfloat16_rn(v.z);
    __nv_bfloat16 h3 = __float2bfloat16_rn(v.w);
    __nv_bfloat16 l0 = __float2bfloat16_rn(v.x - __bfloat162float(h0));
    __nv_bfloat16 l1 = __float2bfloat16_rn(v.y - __bfloat162float(h1));
    __nv_bfloat16 l2 = __float2bfloat16_rn(v.z - __bfloat162float(h2));
    __nv_bfloat16 l3 = __float2bfloat16_rn(v.w - __bfloat162float(h3));
    __nv_bfloat162* ph = (__nv_bfloat162*)&g_xhi[i];
    __nv_bfloat162* pl = (__nv_bfloat162*)&g_xlo[i];
    ph[0] = __halves2bfloat162(h0, h1);
    ph[1] = __halves2bfloat162(h2, h3);
    pl[0] = __halves2bfloat162(l0, l1);
    pl[1] = __halves2bfloat162(l2, l3);
}

// ---------------------------------------------------------------------------
// Kernel 0b: Wq/Wk/Wv -> hi bf16 (all 3); lo bf16 only for Wq
// ---------------------------------------------------------------------------
__global__ __launch_bounds__(256) void cvt_w(const float* __restrict__ Wq,
                                             const float* __restrict__ Wk,
                                             const float* __restrict__ Wv)
{
    size_t e = ((size_t)blockIdx.x * 256 + threadIdx.x) * 4;   // < 786432
    int z = (int)(e >> 18);
    size_t off = e & 262143;
    const float* W = (z == 0) ? Wq : (z == 1 ? Wk : Wv);
    float4 v = *(const float4*)(W + off);
    __nv_bfloat16 h0 = __float2bfloat16_rn(v.x);
    __nv_bfloat16 h1 = __float2bfloat16_rn(v.y);
    __nv_bfloat16 h2 = __float2bfloat16_rn(v.z);
    __nv_bfloat16 h3 = __float2bfloat16_rn(v.w);
    __nv_bfloat162* ph = (__nv_bfloat162*)&g_whi[e];
    ph[0] = __halves2bfloat162(h0, h1);
    ph[1] = __halves2bfloat162(h2, h3);
    if (z == 0) {
        __nv_bfloat16 l0 = __float2bfloat16_rn(v.x - __bfloat162float(h0));
        __nv_bfloat16 l1 = __float2bfloat16_rn(v.y - __bfloat162float(h1));
        __nv_bfloat16 l2 = __float2bfloat16_rn(v.z - __bfloat162float(h2));
        __nv_bfloat16 l3 = __float2bfloat16_rn(v.w - __bfloat162float(h3));
        __nv_bfloat162* pl = (__nv_bfloat162*)&g_wlo[off];
        pl[0] = __halves2bfloat162(l0, l1);
        pl[1] = __halves2bfloat162(l2, l3);
    }
}

// ---------------------------------------------------------------------------
// GEMM geometry: CTA 128x128, BK=32, 8 warps 4x2, warp tile 32x64.
// Smem rows padded to 80B -> ldmatrix conflict-free.
// q: 3-stage pipeline of 4-tile stages; kv: 4-stage pipeline of 2-tile stages.
// ---------------------------------------------------------------------------
#define ROWB    80
#define TILEB   (128 * ROWB)     // 10240
#define BUFB_Q  (4 * TILEB)      // Ahi, Alo, Bhi, Blo
#define NST_Q   3
#define SMEMB_Q (NST_Q * BUFB_Q)     // 122880
#define BUFB_KV (2 * TILEB)      // Ahi, Bhi
#define NST_KV  4
#define SMEMB_KV (NST_KV * BUFB_KV)  // 81920

// ---------------------------------------------------------------------------
// Kernel 1a: q = Xhi*Whi + Xhi*Wlo + Xlo*Whi (3-term, fp32 out)
// ---------------------------------------------------------------------------
__global__ __launch_bounds__(256) void gemm_q()
{
    extern __shared__ char smc[];
    const uint32_t sb = smem_u32(smc);
    const int tid  = threadIdx.x;
    const int wid  = tid >> 5;
    const int lane = tid & 31;
    const int it = blockIdx.x * 128;
    const int jt = blockIdx.y * 128;

    const __nv_bfloat16* xh = g_xhi;
    const __nv_bfloat16* xl = g_xlo;
    const __nv_bfloat16* wh = g_whi;
    const __nv_bfloat16* wl = g_wlo;

    const int wm = (wid >> 1) * 32;
    const int wn = (wid & 1) * 64;

    float acc[2][8][4];
    #pragma unroll
    for (int a = 0; a < 2; a++)
        #pragma unroll
        for (int b = 0; b < 8; b++)
            #pragma unroll
            for (int c = 0; c < 4; c++) acc[a][b][c] = 0.f;

    const int r0c = tid >> 2;
    const int c0  = tid & 3;
    const int r1c = (tid + 256) >> 2;
    const int c1  = (tid + 256) & 3;

#define ISSUE_Q(buf, k0) do { \
    uint32_t base = sb + (uint32_t)(buf) * BUFB_Q; \
    uint32_t s0 = base + r0c * ROWB + c0 * 16; \
    uint32_t s1 = base + r1c * ROWB + c1 * 16; \
    size_t gA0 = (size_t)(it + r0c) * DIMF + (k0) + c0 * 8; \
    size_t gA1 = (size_t)(it + r1c) * DIMF + (k0) + c1 * 8; \
    size_t gB0 = (size_t)(jt + r0c) * DIMF + (k0) + c0 * 8; \
    size_t gB1 = (size_t)(jt + r1c) * DIMF + (k0) + c1 * 8; \
    CP16(s0,             xh + gA0); CP16(s1,             xh + gA1); \
    CP16(s0 + TILEB,     xl + gA0); CP16(s1 + TILEB,     xl + gA1); \
    CP16(s0 + 2 * TILEB, wh + gB0); CP16(s1 + 2 * TILEB, wh + gB1); \
    CP16(s0 + 3 * TILEB, wl + gB0); CP16(s1 + 3 * TILEB, wl + gB1); \
} while (0)

    // prologue: stages 0..NST_Q-2
    ISSUE_Q(0, 0);  CP_COMMIT();
    ISSUE_Q(1, 32); CP_COMMIT();

    #pragma unroll 1
    for (int i = 0; i < 16; i++) {
        CP_WAITG(NST_Q - 2);        // stage i resident
        __syncthreads();            // all warps done with buf (i-1)%NST
        const int nk = i + NST_Q - 1;
        if (nk < 16) ISSUE_Q(nk % NST_Q, nk * 32);
        CP_COMMIT();

        const uint32_t b0 = sb + (uint32_t)(i % NST_Q) * BUFB_Q;
        #pragma unroll
        for (int ks = 0; ks < 2; ks++) {
            const int kb = ks * 32;
            uint32_t ah[2][4], al[2][4], bh[8][2], bl[8][2];
            #pragma unroll
            for (int mf = 0; mf < 2; mf++) {
                uint32_t addr = b0 + (uint32_t)(wm + mf * 16 + (lane & 15)) * ROWB
                              + kb + ((lane >> 4) << 4);
                LDSM4(ah[mf], addr);
                LDSM4(al[mf], addr + TILEB);
            }
            #pragma unroll
            for (int nq = 0; nq < 4; nq++) {
                uint32_t row = (uint32_t)(wn + nq * 16 + (lane & 7) + ((lane >> 4) << 3));
                uint32_t addr = b0 + 2 * TILEB + row * ROWB + kb + (((lane >> 3) & 1) << 4);
                uint32_t t[4];
                LDSM4(t, addr);
                bh[nq * 2][0] = t[0]; bh[nq * 2][1] = t[1];
                bh[nq * 2 + 1][0] = t[2]; bh[nq * 2 + 1][1] = t[3];
                LDSM4(t, addr + TILEB);
                bl[nq * 2][0] = t[0]; bl[nq * 2][1] = t[1];
                bl[nq * 2 + 1][0] = t[2]; bl[nq * 2 + 1][1] = t[3];
            }
            #pragma unroll
            for (int mf = 0; mf < 2; mf++)
                #pragma unroll
                for (int nf = 0; nf < 8; nf++) {
                    MMA16816(acc[mf][nf], ah[mf], bh[nf]);
                    MMA16816(acc[mf][nf], ah[mf], bl[nf]);
                    MMA16816(acc[mf][nf], al[mf], bh[nf]);
                }
        }
    }

    #pragma unroll
    for (int mf = 0; mf < 2; mf++) {
        const int row = it + wm + mf * 16 + (lane >> 2);
        #pragma unroll
        for (int nf = 0; nf < 8; nf++) {
            const int col = jt + wn + nf * 8 + (lane & 3) * 2;
            *(float2*)&g_q[(size_t)row * DIMF + col] =
                make_float2(acc[mf][nf][0], acc[mf][nf][1]);
            *(float2*)&g_q[(size_t)(row + 8) * DIMF + col] =
                make_float2(acc[mf][nf][2], acc[mf][nf][3]);
        }
    }
#undef ISSUE_Q
}

// ---------------------------------------------------------------------------
// Kernel 1b: k/v = Xhi*Whi (1-term, bf16 out). blockIdx.z: 0->k, 1->v.
// ---------------------------------------------------------------------------
__global__ __launch_bounds__(256) void gemm_kv()
{
    extern __shared__ char smc[];
    const uint32_t sb = smem_u32(smc);
    const int tid  = threadIdx.x;
    const int wid  = tid >> 5;
    const int lane = tid & 31;
    const int it = blockIdx.x * 128;
    const int jt = blockIdx.y * 128;
    const int z  = blockIdx.z + 1;           // 1 = k, 2 = v

    const __nv_bfloat16* xh = g_xhi;
    const __nv_bfloat16* wh = g_whi + (size_t)z * DIMF * DIMF;
    __nv_bfloat16* out = (z == 1) ? g_kb : g_vb;

    const int wm = (wid >> 1) * 32;
    const int wn = (wid & 1) * 64;

    float acc[2][8][4];
    #pragma unroll
    for (int a = 0; a < 2; a++)
        #pragma unroll
        for (int b = 0; b < 8; b++)
            #pragma unroll
            for (int c = 0; c < 4; c++) acc[a][b][c] = 0.f;

    const int r0c = tid >> 2;
    const int c0  = tid & 3;
    const int r1c = (tid + 256) >> 2;
    const int c1  = (tid + 256) & 3;

#define ISSUE_KV(buf, k0) do { \
    uint32_t base = sb + (uint32_t)(buf) * BUFB_KV; \
    uint32_t s0 = base + r0c * ROWB + c0 * 16; \
    uint32_t s1 = base + r1c * ROWB + c1 * 16; \
    CP16(s0,         xh + (size_t)(it + r0c) * DIMF + (k0) + c0 * 8); \
    CP16(s1,         xh + (size_t)(it + r1c) * DIMF + (k0) + c1 * 8); \
    CP16(s0 + TILEB, wh + (size_t)(jt + r0c) * DIMF + (k0) + c0 * 8); \
    CP16(s1 + TILEB, wh + (size_t)(jt + r1c) * DIMF + (k0) + c1 * 8); \
} while (0)

    // prologue: stages 0..NST_KV-2
    ISSUE_KV(0, 0);  CP_COMMIT();
    ISSUE_KV(1, 32); CP_COMMIT();
    ISSUE_KV(2, 64); CP_COMMIT();

    #pragma unroll 1
    for (int i = 0; i < 16; i++) {
        CP_WAITG(NST_KV - 2);
        __syncthreads();
        const int nk = i + NST_KV - 1;
        if (nk < 16) ISSUE_KV(nk % NST_KV, nk * 32);
        CP_COMMIT();

        const uint32_t b0 = sb + (uint32_t)(i % NST_KV) * BUFB_KV;
        #pragma unroll
        for (int ks = 0; ks < 2; ks++) {
            const int kb = ks * 32;
            uint32_t ah[2][4], bh[8][2];
            #pragma unroll
            for (int mf = 0; mf < 2; mf++) {
                uint32_t addr = b0 + (uint32_t)(wm + mf * 16 + (lane & 15)) * ROWB
                              + kb + ((lane >> 4) << 4);
                LDSM4(ah[mf], addr);
            }
            #pragma unroll
            for (int nq = 0; nq < 4; nq++) {
                uint32_t row = (uint32_t)(wn + nq * 16 + (lane & 7) + ((lane >> 4) << 3));
                uint32_t addr = b0 + TILEB + row * ROWB + kb + (((lane >> 3) & 1) << 4);
                uint32_t t[4];
                LDSM4(t, addr);
                bh[nq * 2][0] = t[0]; bh[nq * 2][1] = t[1];
                bh[nq * 2 + 1][0] = t[2]; bh[nq * 2 + 1][1] = t[3];
            }
            #pragma unroll
            for (int mf = 0; mf < 2; mf++)
                #pragma unroll
                for (int nf = 0; nf < 8; nf++)
                    MMA16816(acc[mf][nf], ah[mf], bh[nf]);
        }
    }

    #pragma unroll
    for (int mf = 0; mf < 2; mf++) {
        const int row = it + wm + mf * 16 + (lane >> 2);
        #pragma unroll
        for (int nf = 0; nf < 8; nf++) {
            const int col = jt + wn + nf * 8 + (lane & 3) * 2;
            *(__nv_bfloat162*)&out[(size_t)row * DIMF + col] =
                __floats2bfloat162_rn(acc[mf][nf][0], acc[mf][nf][1]);
            *(__nv_bfloat162*)&out[(size_t)(row + 8) * DIMF + col] =
                __floats2bfloat162_rn(acc[mf][nf][2], acc[mf][nf][3]);
        }
    }
#undef ISSUE_KV
}

// ---------------------------------------------------------------------------
// Kernel 2: per (b,s,h): global_query then global_key.
// No max-subtraction (logits ~1e-3); k read as bf16.
// ---------------------------------------------------------------------------
__global__ __launch_bounds__(256) void global_qk(
    const float* __restrict__ w_alpha,
    const float* __restrict__ w_beta)
{
    const int bsh = blockIdx.x;            // 0..2047
    const int bs  = bsh >> 3;
    const int h   = bsh & 7;
    const size_t base = ((size_t)bs * N_PER) * DIMF + (size_t)h * DH;

    const int tid  = threadIdx.x;
    const int warp = tid >> 5;
    const int lane = tid & 31;

    __shared__ float s_red[8][64];
    __shared__ float s_gq[64];

    // ---- pass 1: global_query from q (fp32) ----
    const float wa0 = w_alpha[lane]      * SCALE_F;
    const float wa1 = w_alpha[lane + 32] * SCALE_F;
    float acc0 = 0.f, acc1 = 0.f;
    for (int n = warp; n < N_PER; n += 8) {
        const float* qr = &g_q[base + (size_t)n * DIMF];
        const float q0 = qr[lane], q1 = qr[lane + 32];
        float e0 = __expf(q0 * wa0), e1 = __expf(q1 * wa1);
        float s = e0 + e1;
        #pragma unroll
        for (int o = 16; o > 0; o >>= 1) s += __shfl_xor_sync(~0u, s, o);
        const float inv = 1.f / s;
        acc0 += q0 * e0 * inv;
        acc1 += q1 * e1 * inv;
    }
    s_red[warp][lane]      = acc0;
    s_red[warp][lane + 32] = acc1;
    __syncthreads();
    if (tid < 64) {
        float s = 0.f;
        #pragma unroll
        for (int w = 0; w < 8; w++) s += s_red[w][tid];
        s_gq[tid] = s;
    }
    __syncthreads();

    // ---- pass 2: global_key from p = gq * k (bf16 k, paired lanes) ----
    const float wb0 = w_beta[2 * lane]     * SCALE_F;
    const float wb1 = w_beta[2 * lane + 1] * SCALE_F;
    const float gq0 = s_gq[2 * lane], gq1 = s_gq[2 * lane + 1];
    acc0 = 0.f; acc1 = 0.f;
    for (int n = warp; n < N_PER; n += 8) {
        __nv_bfloat162 kk = *(const __nv_bfloat162*)&g_kb[base + (size_t)n * DIMF + 2 * lane];
        const float p0 = gq0 * __bfloat162float(kk.x);
        const float p1 = gq1 * __bfloat162float(kk.y);
        float e0 = __expf(p0 * wb0), e1 = __expf(p1 * wb1);
        float s = e0 + e1;
        #pragma unroll
        for (int o = 16; o > 0; o >>= 1) s += __shfl_xor_sync(~0u, s, o);
        const float inv = 1.f / s;
        acc0 += p0 * e0 * inv;
        acc1 += p1 * e1 * inv;
    }
    __syncthreads();
    s_red[warp][2 * lane]     = acc0;
    s_red[warp][2 * lane + 1] = acc1;
    __syncthreads();
    if (tid < 64) {
        float s = 0.f;
        #pragma unroll
        for (int w = 0; w < 8; w++) s += s_red[w][tid];
        g_gk[bsh * DH + tid] = s;
    }
}

// ---------------------------------------------------------------------------
// Kernel 3: epilogue, 16 tokens per block; v read as bf16.
// ---------------------------------------------------------------------------
__global__ __launch_bounds__(256) void epilogue(
    const float* __restrict__ Wr,
    float* __restrict__ out)
{
    __shared__ float wr[64][64];     // wr[i][j] = Wr[j][i]
    __shared__ float kv[8][64];

    const int tid = threadIdx.x;
    for (int idx = tid; idx < 4096; idx += 256) {
        wr[idx & 63][idx >> 6] = Wr[idx];
    }
    __syncthreads();

    const int warp = tid >> 5;       // head h
    const int lane = tid & 31;
    const int t0   = blockIdx.x * 16;
    const int bsh  = ((t0 >> 8) << 3) + warp;
    const float gk0 = g_gk[bsh * DH + 2 * lane];
    const float gk1 = g_gk[bsh * DH + 2 * lane + 1];

    for (int rep = 0; rep < 16; rep++) {
        const int t = t0 + rep;
        const size_t off = (size_t)t * DIMF + (size_t)warp * DH;
        __nv_bfloat162 vv = *(const __nv_bfloat162*)&g_vb[off + 2 * lane];
        kv[warp][2 * lane]     = gk0 * __bfloat162float(vv.x);
        kv[warp][2 * lane + 1] = gk1 * __bfloat162float(vv.y);
        __syncwarp();

        float o0 = g_q[off + lane];
        float o1 = g_q[off + lane + 32];
        #pragma unroll
        for (int i = 0; i < 64; i++) {
            const float kvi = kv[warp][i];
            o0 += kvi * wr[i][lane];
            o1 += kvi * wr[i][lane + 32];
        }
        out[off + lane]      = o0;
        out[off + lane + 32] = o1;
        __syncwarp();
    }
}

// ---------------------------------------------------------------------------
extern "C" void kernel_launch(void* const* d_in, const int* in_sizes, int n_in,
                              void* d_out, int out_size)
{
    const float* x       = (const float*)d_in[0];
    const float* Wq      = (const float*)d_in[1];
    const float* Wk      = (const float*)d_in[2];
    const float* Wv      = (const float*)d_in[3];
    const float* Wr      = (const float*)d_in[4];
    const float* w_alpha = (const float*)d_in[5];
    const float* w_beta  = (const float*)d_in[6];
    float* out = (float*)d_out;

    static int smem_set = 0;
    if (!smem_set) {
        cudaFuncSetAttribute(gemm_q,
                             cudaFuncAttributeMaxDynamicSharedMemorySize, SMEMB_Q);
        cudaFuncSetAttribute(gemm_kv,
                             cudaFuncAttributeMaxDynamicSharedMemorySize, SMEMB_KV);
        smem_set = 1;
    }

    cvt_x<<<32768, 256>>>(x);
    cvt_w<<<768, 256>>>(Wq, Wk, Wv);

    dim3 gq(T_TOK / 128, DIMF / 128);
    gemm_q<<<gq, 256, SMEMB_Q>>>();

    dim3 gkv(T_TOK / 128, DIMF / 128, 2);
    gemm_kv<<<gkv, 256, SMEMB_KV>>>();

    global_qk<<<BSCNT * NHEADS, 256>>>(w_alpha, w_beta);

    epilogue<<<T_TOK / 16, 256>>>(Wr, out);
}

// round 10
// speedup vs baseline: 1.2696x; 1.2696x over previous
#include <cuda_runtime.h>
#include <cuda_bf16.h>
#include <cuda_fp16.h>
#include <stdint.h>

// Problem constants
#define T_TOK   65536          // B*S*N tokens
#define DIMF    512
#define NHEADS  8
#define DH      64
#define N_PER   256
#define BSCNT   256
#define SCALE_F 0.044194173824159216f   // 512^-0.5

// Scratch (device globals: allocation-free per harness rules)
__device__ float g_q[(size_t)T_TOK * DIMF];
__device__ __nv_bfloat16 g_kb[(size_t)T_TOK * DIMF];
__device__ __nv_bfloat16 g_vb[(size_t)T_TOK * DIMF];
__device__ float g_gk[BSCNT * NHEADS * DH];
__device__ __half g_xh[(size_t)T_TOK * DIMF];
__device__ __half g_wh[3 * DIMF * DIMF];

// ---------------------------------------------------------------------------
// PTX helpers
// ---------------------------------------------------------------------------
__device__ __forceinline__ uint32_t smem_u32(const void* p) {
    uint32_t a;
    asm("{ .reg .u64 t; cvta.to.shared.u64 t, %1; cvt.u32.u64 %0, t; }" : "=r"(a) : "l"(p));
    return a;
}
#define CP16(s, g) asm volatile("cp.async.cg.shared.global [%0], [%1], 16;" :: "r"(s), "l"(g))
#define CP_COMMIT() asm volatile("cp.async.commit_group;")
#define CP_WAITG(n) asm volatile("cp.async.wait_group %0;" :: "n"(n))

#define LDSM4(r, a) \
    asm volatile("ldmatrix.sync.aligned.m8n8.x4.shared.b16 {%0,%1,%2,%3}, [%4];" \
        : "=r"((r)[0]), "=r"((r)[1]), "=r"((r)[2]), "=r"((r)[3]) : "r"(a))

#define MMA16816F(d, a, b) \
    asm volatile("mma.sync.aligned.m16n8k16.row.col.f32.f16.f16.f32 " \
        "{%0,%1,%2,%3}, {%4,%5,%6,%7}, {%8,%9}, {%0,%1,%2,%3};" \
        : "+f"((d)[0]), "+f"((d)[1]), "+f"((d)[2]), "+f"((d)[3]) \
        : "r"((a)[0]), "r"((a)[1]), "r"((a)[2]), "r"((a)[3]), "r"((b)[0]), "r"((b)[1]))

// ---------------------------------------------------------------------------
// Kernel 0a: x (fp32) -> fp16
// ---------------------------------------------------------------------------
__global__ __launch_bounds__(256) void cvt_x(const float* __restrict__ x)
{
    size_t i = ((size_t)blockIdx.x * 256 + threadIdx.x) * 4;
    float4 v = *(const float4*)(x + i);
    __half2* ph = (__half2*)&g_xh[i];
    ph[0] = __floats2half2_rn(v.x, v.y);
    ph[1] = __floats2half2_rn(v.z, v.w);
}

// ---------------------------------------------------------------------------
// Kernel 0b: Wq/Wk/Wv -> fp16 (concatenated [3][512*512])
// ---------------------------------------------------------------------------
__global__ __launch_bounds__(256) void cvt_w(const float* __restrict__ Wq,
                                             const float* __restrict__ Wk,
                                             const float* __restrict__ Wv)
{
    size_t e = ((size_t)blockIdx.x * 256 + threadIdx.x) * 4;   // < 786432
    int z = (int)(e >> 18);
    size_t off = e & 262143;
    const float* W = (z == 0) ? Wq : (z == 1 ? Wk : Wv);
    float4 v = *(const float4*)(W + off);
    __half2* ph = (__half2*)&g_wh[e];
    ph[0] = __floats2half2_rn(v.x, v.y);
    ph[1] = __floats2half2_rn(v.z, v.w);
}

// ---------------------------------------------------------------------------
// Fused QKV GEMM (fp16, 1-term): CTA 128x128, BK=32, 8 warps 4x2,
// warp tile 32x64, 4-stage cp.async pipeline.
// blockIdx.z: 0 -> q (fp32 out), 1 -> k (bf16 out), 2 -> v (bf16 out).
// Smem rows padded to 80B -> ldmatrix conflict-free.
// ---------------------------------------------------------------------------
#define ROWB    80
#define TILEB   (128 * ROWB)        // 10240
#define BUFB    (2 * TILEB)         // A, B
#define NST     4
#define SMEMB   (NST * BUFB)        // 81920

__global__ __launch_bounds__(256) void gemm_qkv()
{
    extern __shared__ char smc[];
    const uint32_t sb = smem_u32(smc);
    const int tid  = threadIdx.x;
    const int wid  = tid >> 5;
    const int lane = tid & 31;
    const int it = blockIdx.x * 128;
    const int jt = blockIdx.y * 128;
    const int z  = blockIdx.z;

    const __half* xh = g_xh;
    const __half* wh = g_wh + (size_t)z * DIMF * DIMF;

    const int wm = (wid >> 1) * 32;
    const int wn = (wid & 1) * 64;

    float acc[2][8][4];
    #pragma unroll
    for (int a = 0; a < 2; a++)
        #pragma unroll
        for (int b = 0; b < 8; b++)
            #pragma unroll
            for (int c = 0; c < 4; c++) acc[a][b][c] = 0.f;

    const int r0c = tid >> 2;
    const int c0  = tid & 3;
    const int r1c = (tid + 256) >> 2;
    const int c1  = (tid + 256) & 3;

#define ISSUE(buf, k0) do { \
    uint32_t base = sb + (uint32_t)(buf) * BUFB; \
    uint32_t s0 = base + r0c * ROWB + c0 * 16; \
    uint32_t s1 = base + r1c * ROWB + c1 * 16; \
    CP16(s0,         xh + (size_t)(it + r0c) * DIMF + (k0) + c0 * 8); \
    CP16(s1,         xh + (size_t)(it + r1c) * DIMF + (k0) + c1 * 8); \
    CP16(s0 + TILEB, wh + (size_t)(jt + r0c) * DIMF + (k0) + c0 * 8); \
    CP16(s1 + TILEB, wh + (size_t)(jt + r1c) * DIMF + (k0) + c1 * 8); \
} while (0)

    ISSUE(0, 0);  CP_COMMIT();
    ISSUE(1, 32); CP_COMMIT();
    ISSUE(2, 64); CP_COMMIT();

    #pragma unroll 1
    for (int i = 0; i < 16; i++) {
        CP_WAITG(NST - 2);
        __syncthreads();
        const int nk = i + NST - 1;
        if (nk < 16) ISSUE(nk % NST, nk * 32);
        CP_COMMIT();

        const uint32_t b0 = sb + (uint32_t)(i % NST) * BUFB;
        #pragma unroll
        for (int ks = 0; ks < 2; ks++) {
            const int kb = ks * 32;
            uint32_t ah[2][4], bh[8][2];
            #pragma unroll
            for (int mf = 0; mf < 2; mf++) {
                uint32_t addr = b0 + (uint32_t)(wm + mf * 16 + (lane & 15)) * ROWB
                              + kb + ((lane >> 4) << 4);
                LDSM4(ah[mf], addr);
            }
            #pragma unroll
            for (int nq = 0; nq < 4; nq++) {
                uint32_t row = (uint32_t)(wn + nq * 16 + (lane & 7) + ((lane >> 4) << 3));
                uint32_t addr = b0 + TILEB + row * ROWB + kb + (((lane >> 3) & 1) << 4);
                uint32_t t[4];
                LDSM4(t, addr);
                bh[nq * 2][0] = t[0]; bh[nq * 2][1] = t[1];
                bh[nq * 2 + 1][0] = t[2]; bh[nq * 2 + 1][1] = t[3];
            }
            #pragma unroll
            for (int mf = 0; mf < 2; mf++)
                #pragma unroll
                for (int nf = 0; nf < 8; nf++)
                    MMA16816F(acc[mf][nf], ah[mf], bh[nf]);
        }
    }
#undef ISSUE

    if (z == 0) {
        #pragma unroll
        for (int mf = 0; mf < 2; mf++) {
            const int row = it + wm + mf * 16 + (lane >> 2);
            #pragma unroll
            for (int nf = 0; nf < 8; nf++) {
                const int col = jt + wn + nf * 8 + (lane & 3) * 2;
                *(float2*)&g_q[(size_t)row * DIMF + col] =
                    make_float2(acc[mf][nf][0], acc[mf][nf][1]);
                *(float2*)&g_q[(size_t)(row + 8) * DIMF + col] =
                    make_float2(acc[mf][nf][2], acc[mf][nf][3]);
            }
        }
    } else {
        __nv_bfloat16* out = (z == 1) ? g_kb : g_vb;
        #pragma unroll
        for (int mf = 0; mf < 2; mf++) {
            const int row = it + wm + mf * 16 + (lane >> 2);
            #pragma unroll
            for (int nf = 0; nf < 8; nf++) {
                const int col = jt + wn + nf * 8 + (lane & 3) * 2;
                *(__nv_bfloat162*)&out[(size_t)row * DIMF + col] =
                    __floats2bfloat162_rn(acc[mf][nf][0], acc[mf][nf][1]);
                *(__nv_bfloat162*)&out[(size_t)(row + 8) * DIMF + col] =
                    __floats2bfloat162_rn(acc[mf][nf][2], acc[mf][nf][3]);
            }
        }
    }
}

// ---------------------------------------------------------------------------
// Kernel 2: per (b,s,h): global_query then global_key.
// No max-subtraction (logits ~1e-3); k read as bf16.
// ---------------------------------------------------------------------------
__global__ __launch_bounds__(256) void global_qk(
    const float* __restrict__ w_alpha,
    const float* __restrict__ w_beta)
{
    const int bsh = blockIdx.x;            // 0..2047
    const int bs  = bsh >> 3;
    const int h   = bsh & 7;
    const size_t base = ((size_t)bs * N_PER) * DIMF + (size_t)h * DH;

    const int tid  = threadIdx.x;
    const int warp = tid >> 5;
    const int lane = tid & 31;

    __shared__ float s_red[8][64];
    __shared__ float s_gq[64];

    // ---- pass 1: global_query from q (fp32) ----
    const float wa0 = w_alpha[lane]      * SCALE_F;
    const float wa1 = w_alpha[lane + 32] * SCALE_F;
    float acc0 = 0.f, acc1 = 0.f;
    for (int n = warp; n < N_PER; n += 8) {
        const float* qr = &g_q[base + (size_t)n * DIMF];
        const float q0 = qr[lane], q1 = qr[lane + 32];
        float e0 = __expf(q0 * wa0), e1 = __expf(q1 * wa1);
        float s = e0 + e1;
        #pragma unroll
        for (int o = 16; o > 0; o >>= 1) s += __shfl_xor_sync(~0u, s, o);
        const float inv = 1.f / s;
        acc0 += q0 * e0 * inv;
        acc1 += q1 * e1 * inv;
    }
    s_red[warp][lane]      = acc0;
    s_red[warp][lane + 32] = acc1;
    __syncthreads();
    if (tid < 64) {
        float s = 0.f;
        #pragma unroll
        for (int w = 0; w < 8; w++) s += s_red[w][tid];
        s_gq[tid] = s;
    }
    __syncthreads();

    // ---- pass 2: global_key from p = gq * k (bf16 k, paired lanes) ----
    const float wb0 = w_beta[2 * lane]     * SCALE_F;
    const float wb1 = w_beta[2 * lane + 1] * SCALE_F;
    const float gq0 = s_gq[2 * lane], gq1 = s_gq[2 * lane + 1];
    acc0 = 0.f; acc1 = 0.f;
    for (int n = warp; n < N_PER; n += 8) {
        __nv_bfloat162 kk = *(const __nv_bfloat162*)&g_kb[base + (size_t)n * DIMF + 2 * lane];
        const float p0 = gq0 * __bfloat162float(kk.x);
        const float p1 = gq1 * __bfloat162float(kk.y);
        float e0 = __expf(p0 * wb0), e1 = __expf(p1 * wb1);
        float s = e0 + e1;
        #pragma unroll
        for (int o = 16; o > 0; o >>= 1) s += __shfl_xor_sync(~0u, s, o);
        const float inv = 1.f / s;
        acc0 += p0 * e0 * inv;
        acc1 += p1 * e1 * inv;
    }
    __syncthreads();
    s_red[warp][2 * lane]     = acc0;
    s_red[warp][2 * lane + 1] = acc1;
    __syncthreads();
    if (tid < 64) {
        float s = 0.f;
        #pragma unroll
        for (int w = 0; w < 8; w++) s += s_red[w][tid];
        g_gk[bsh * DH + tid] = s;
    }
}

// ---------------------------------------------------------------------------
// Kernel 3: epilogue, 16 tokens per block; v read as bf16.
// ---------------------------------------------------------------------------
__global__ __launch_bounds__(256) void epilogue(
    const float* __restrict__ Wr,
    float* __restrict__ out)
{
    __shared__ float wr[64][64];     // wr[i][j] = Wr[j][i]
    __shared__ float kv[8][64];

    const int tid = threadIdx.x;
    for (int idx = tid; idx < 4096; idx += 256) {
        wr[idx & 63][idx >> 6] = Wr[idx];
    }
    __syncthreads();

    const int warp = tid >> 5;       // head h
    const int lane = tid & 31;
    const int t0   = blockIdx.x * 16;
    const int bsh  = ((t0 >> 8) << 3) + warp;
    const float gk0 = g_gk[bsh * DH + 2 * lane];
    const float gk1 = g_gk[bsh * DH + 2 * lane + 1];

    for (int rep = 0; rep < 16; rep++) {
        const int t = t0 + rep;
        const size_t off = (size_t)t * DIMF + (size_t)warp * DH;
        __nv_bfloat162 vv = *(const __nv_bfloat162*)&g_vb[off + 2 * lane];
        kv[warp][2 * lane]     = gk0 * __bfloat162float(vv.x);
        kv[warp][2 * lane + 1] = gk1 * __bfloat162float(vv.y);
        __syncwarp();

        float o0 = g_q[off + lane];
        float o1 = g_q[off + lane + 32];
        #pragma unroll
        for (int i = 0; i < 64; i++) {
            const float kvi = kv[warp][i];
            o0 += kvi * wr[i][lane];
            o1 += kvi * wr[i][lane + 32];
        }
        out[off + lane]      = o0;
        out[off + lane + 32] = o1;
        __syncwarp();
    }
}

// ---------------------------------------------------------------------------
extern "C" void kernel_launch(void* const* d_in, const int* in_sizes, int n_in,
                              void* d_out, int out_size)
{
    const float* x       = (const float*)d_in[0];
    const float* Wq      = (const float*)d_in[1];
    const float* Wk      = (const float*)d_in[2];
    const float* Wv      = (const float*)d_in[3];
    const float* Wr      = (const float*)d_in[4];
    const float* w_alpha = (const float*)d_in[5];
    const float* w_beta  = (const float*)d_in[6];
    float* out = (float*)d_out;

    static int smem_set = 0;
    if (!smem_set) {
        cudaFuncSetAttribute(gemm_qkv,
                             cudaFuncAttributeMaxDynamicSharedMemorySize, SMEMB);
        smem_set = 1;
    }

    cvt_x<<<32768, 256>>>(x);
    cvt_w<<<768, 256>>>(Wq, Wk, Wv);

    dim3 g1(T_TOK / 128, DIMF / 128, 3);
    gemm_qkv<<<g1, 256, SMEMB>>>();

    global_qk<<<BSCNT * NHEADS, 256>>>(w_alpha, w_beta);

    epilogue<<<T_TOK / 16, 256>>>(Wr, out);
}

// round 12
// speedup vs baseline: 1.7002x; 1.3392x over previous
#include <cuda_runtime.h>
#include <cuda_bf16.h>
#include <cuda_fp16.h>
#include <stdint.h>

// Problem constants
#define T_TOK   65536          // B*S*N tokens
#define DIMF    512
#define NHEADS  8
#define DH      64
#define N_PER   256
#define BSCNT   256
#define SCALE_F 0.044194173824159216f   // 512^-0.5

// Scratch (device globals: allocation-free per harness rules)
__device__ float g_q[(size_t)T_TOK * DIMF];
__device__ __half g_kh[(size_t)T_TOK * DIMF];
__device__ __half g_vh[(size_t)T_TOK * DIMF];
__device__ float g_gk[BSCNT * NHEADS * DH];
__device__ __half g_xh[(size_t)T_TOK * DIMF];
__device__ __half g_wh[3 * DIMF * DIMF];

// ---------------------------------------------------------------------------
// PTX helpers
// ---------------------------------------------------------------------------
__device__ __forceinline__ uint32_t smem_u32(const void* p) {
    uint32_t a;
    asm("{ .reg .u64 t; cvta.to.shared.u64 t, %1; cvt.u32.u64 %0, t; }" : "=r"(a) : "l"(p));
    return a;
}
#define CP16(s, g) asm volatile("cp.async.cg.shared.global [%0], [%1], 16;" :: "r"(s), "l"(g))
#define CP_COMMIT() asm volatile("cp.async.commit_group;")
#define CP_WAITG(n) asm volatile("cp.async.wait_group %0;" :: "n"(n))

#define LDSM4(r, a) \
    asm volatile("ldmatrix.sync.aligned.m8n8.x4.shared.b16 {%0,%1,%2,%3}, [%4];" \
        : "=r"((r)[0]), "=r"((r)[1]), "=r"((r)[2]), "=r"((r)[3]) : "r"(a))

#define MMA16816F(d, a, b) \
    asm volatile("mma.sync.aligned.m16n8k16.row.col.f32.f16.f16.f32 " \
        "{%0,%1,%2,%3}, {%4,%5,%6,%7}, {%8,%9}, {%0,%1,%2,%3};" \
        : "+f"((d)[0]), "+f"((d)[1]), "+f"((d)[2]), "+f"((d)[3]) \
        : "r"((a)[0]), "r"((a)[1]), "r"((a)[2]), "r"((a)[3]), "r"((b)[0]), "r"((b)[1]))

__device__ __forceinline__ uint32_t h2u(__half2 h) {
    uint32_t u; asm("mov.b32 %0, %1;" : "=r"(u) : "r"(*(uint32_t*)&h)); return u;
}

// ---------------------------------------------------------------------------
// Kernel 0a: x (fp32) -> fp16
// ---------------------------------------------------------------------------
__global__ __launch_bounds__(256) void cvt_x(const float* __restrict__ x)
{
    size_t i = ((size_t)blockIdx.x * 256 + threadIdx.x) * 4;
    float4 v = *(const float4*)(x + i);
    __half2* ph = (__half2*)&g_xh[i];
    ph[0] = __floats2half2_rn(v.x, v.y);
    ph[1] = __floats2half2_rn(v.z, v.w);
}

// ---------------------------------------------------------------------------
// Kernel 0b: Wq/Wk/Wv -> fp16 (concatenated [3][512*512])
// ---------------------------------------------------------------------------
__global__ __launch_bounds__(256) void cvt_w(const float* __restrict__ Wq,
                                             const float* __restrict__ Wk,
                                             const float* __restrict__ Wv)
{
    size_t e = ((size_t)blockIdx.x * 256 + threadIdx.x) * 4;   // < 786432
    int z = (int)(e >> 18);
    size_t off = e & 262143;
    const float* W = (z == 0) ? Wq : (z == 1 ? Wk : Wv);
    float4 v = *(const float4*)(W + off);
    __half2* ph = (__half2*)&g_wh[e];
    ph[0] = __floats2half2_rn(v.x, v.y);
    ph[1] = __floats2half2_rn(v.z, v.w);
}

// ---------------------------------------------------------------------------
// Fused QKV GEMM (fp16, 1-term): CTA 128x128, BK=32, 8 warps 4x2,
// warp tile 32x64, 4-stage cp.async pipeline.
// blockIdx.z: 0 -> q (fp32 out), 1 -> k (fp16 out), 2 -> v (fp16 out).
// ---------------------------------------------------------------------------
#define ROWB    80
#define TILEB   (128 * ROWB)        // 10240
#define BUFB    (2 * TILEB)         // A, B
#define NST     4
#define SMEMB   (NST * BUFB)        // 81920

__global__ __launch_bounds__(256) void gemm_qkv()
{
    extern __shared__ char smc[];
    const uint32_t sb = smem_u32(smc);
    const int tid  = threadIdx.x;
    const int wid  = tid >> 5;
    const int lane = tid & 31;
    const int it = blockIdx.x * 128;
    const int jt = blockIdx.y * 128;
    const int z  = blockIdx.z;

    const __half* xh = g_xh;
    const __half* wh = g_wh + (size_t)z * DIMF * DIMF;

    const int wm = (wid >> 1) * 32;
    const int wn = (wid & 1) * 64;

    float acc[2][8][4];
    #pragma unroll
    for (int a = 0; a < 2; a++)
        #pragma unroll
        for (int b = 0; b < 8; b++)
            #pragma unroll
            for (int c = 0; c < 4; c++) acc[a][b][c] = 0.f;

    const int r0c = tid >> 2;
    const int c0  = tid & 3;
    const int r1c = (tid + 256) >> 2;
    const int c1  = (tid + 256) & 3;

#define ISSUE(buf, k0) do { \
    uint32_t base = sb + (uint32_t)(buf) * BUFB; \
    uint32_t s0 = base + r0c * ROWB + c0 * 16; \
    uint32_t s1 = base + r1c * ROWB + c1 * 16; \
    CP16(s0,         xh + (size_t)(it + r0c) * DIMF + (k0) + c0 * 8); \
    CP16(s1,         xh + (size_t)(it + r1c) * DIMF + (k0) + c1 * 8); \
    CP16(s0 + TILEB, wh + (size_t)(jt + r0c) * DIMF + (k0) + c0 * 8); \
    CP16(s1 + TILEB, wh + (size_t)(jt + r1c) * DIMF + (k0) + c1 * 8); \
} while (0)

    ISSUE(0, 0);  CP_COMMIT();
    ISSUE(1, 32); CP_COMMIT();
    ISSUE(2, 64); CP_COMMIT();

    #pragma unroll 1
    for (int i = 0; i < 16; i++) {
        CP_WAITG(NST - 2);
        __syncthreads();
        const int nk = i + NST - 1;
        if (nk < 16) ISSUE(nk % NST, nk * 32);
        CP_COMMIT();

        const uint32_t b0 = sb + (uint32_t)(i % NST) * BUFB;
        #pragma unroll
        for (int ks = 0; ks < 2; ks++) {
            const int kb = ks * 32;
            uint32_t ah[2][4], bh[8][2];
            #pragma unroll
            for (int mf = 0; mf < 2; mf++) {
                uint32_t addr = b0 + (uint32_t)(wm + mf * 16 + (lane & 15)) * ROWB
                              + kb + ((lane >> 4) << 4);
                LDSM4(ah[mf], addr);
            }
            #pragma unroll
            for (int nq = 0; nq < 4; nq++) {
                uint32_t row = (uint32_t)(wn + nq * 16 + (lane & 7) + ((lane >> 4) << 3));
                uint32_t addr = b0 + TILEB + row * ROWB + kb + (((lane >> 3) & 1) << 4);
                uint32_t t[4];
                LDSM4(t, addr);
                bh[nq * 2][0] = t[0]; bh[nq * 2][1] = t[1];
                bh[nq * 2 + 1][0] = t[2]; bh[nq * 2 + 1][1] = t[3];
            }
            #pragma unroll
            for (int mf = 0; mf < 2; mf++)
                #pragma unroll
                for (int nf = 0; nf < 8; nf++)
                    MMA16816F(acc[mf][nf], ah[mf], bh[nf]);
        }
    }
#undef ISSUE

    if (z == 0) {
        #pragma unroll
        for (int mf = 0; mf < 2; mf++) {
            const int row = it + wm + mf * 16 + (lane >> 2);
            #pragma unroll
            for (int nf = 0; nf < 8; nf++) {
                const int col = jt + wn + nf * 8 + (lane & 3) * 2;
                *(float2*)&g_q[(size_t)row * DIMF + col] =
                    make_float2(acc[mf][nf][0], acc[mf][nf][1]);
                *(float2*)&g_q[(size_t)(row + 8) * DIMF + col] =
                    make_float2(acc[mf][nf][2], acc[mf][nf][3]);
            }
        }
    } else {
        __half* out = (z == 1) ? g_kh : g_vh;
        #pragma unroll
        for (int mf = 0; mf < 2; mf++) {
            const int row = it + wm + mf * 16 + (lane >> 2);
            #pragma unroll
            for (int nf = 0; nf < 8; nf++) {
                const int col = jt + wn + nf * 8 + (lane & 3) * 2;
                *(__half2*)&out[(size_t)row * DIMF + col] =
                    __floats2half2_rn(acc[mf][nf][0], acc[mf][nf][1]);
                *(__half2*)&out[(size_t)(row + 8) * DIMF + col] =
                    __floats2half2_rn(acc[mf][nf][2], acc[mf][nf][3]);
            }
        }
    }
}

// ---------------------------------------------------------------------------
// Kernel 2: per (b,s,h): global_query then global_key.
// No max-subtraction (logits ~1e-3); k read as fp16.
// ---------------------------------------------------------------------------
__global__ __launch_bounds__(256) void global_qk(
    const float* __restrict__ w_alpha,
    const float* __restrict__ w_beta)
{
    const int bsh = blockIdx.x;            // 0..2047
    const int bs  = bsh >> 3;
    const int h   = bsh & 7;
    const size_t base = ((size_t)bs * N_PER) * DIMF + (size_t)h * DH;

    const int tid  = threadIdx.x;
    const int warp = tid >> 5;
    const int lane = tid & 31;

    __shared__ float s_red[8][64];
    __shared__ float s_gq[64];

    // ---- pass 1: global_query from q (fp32) ----
    const float wa0 = w_alpha[lane]      * SCALE_F;
    const float wa1 = w_alpha[lane + 32] * SCALE_F;
    float acc0 = 0.f, acc1 = 0.f;
    for (int n = warp; n < N_PER; n += 8) {
        const float* qr = &g_q[base + (size_t)n * DIMF];
        const float q0 = qr[lane], q1 = qr[lane + 32];
        float e0 = __expf(q0 * wa0), e1 = __expf(q1 * wa1);
        float s = e0 + e1;
        #pragma unroll
        for (int o = 16; o > 0; o >>= 1) s += __shfl_xor_sync(~0u, s, o);
        const float inv = 1.f / s;
        acc0 += q0 * e0 * inv;
        acc1 += q1 * e1 * inv;
    }
    s_red[warp][lane]      = acc0;
    s_red[warp][lane + 32] = acc1;
    __syncthreads();
    if (tid < 64) {
        float s = 0.f;
        #pragma unroll
        for (int w = 0; w < 8; w++) s += s_red[w][tid];
        s_gq[tid] = s;
    }
    __syncthreads();

    // ---- pass 2: global_key from p = gq * k (fp16 k, paired lanes) ----
    const float wb0 = w_beta[2 * lane]     * SCALE_F;
    const float wb1 = w_beta[2 * lane + 1] * SCALE_F;
    const float gq0 = s_gq[2 * lane], gq1 = s_gq[2 * lane + 1];
    acc0 = 0.f; acc1 = 0.f;
    for (int n = warp; n < N_PER; n += 8) {
        __half2 kk = *(const __half2*)&g_kh[base + (size_t)n * DIMF + 2 * lane];
        const float p0 = gq0 * __half2float(kk.x);
        const float p1 = gq1 * __half2float(kk.y);
        float e0 = __expf(p0 * wb0), e1 = __expf(p1 * wb1);
        float s = e0 + e1;
        #pragma unroll
        for (int o = 16; o > 0; o >>= 1) s += __shfl_xor_sync(~0u, s, o);
        const float inv = 1.f / s;
        acc0 += p0 * e0 * inv;
        acc1 += p1 * e1 * inv;
    }
    __syncthreads();
    s_red[warp][2 * lane]     = acc0;
    s_red[warp][2 * lane + 1] = acc1;
    __syncthreads();
    if (tid < 64) {
        float s = 0.f;
        #pragma unroll
        for (int w = 0; w < 8; w++) s += s_red[w][tid];
        g_gk[bsh * DH + tid] = s;
    }
}

// ---------------------------------------------------------------------------
// Kernel 3: tensor-core epilogue.
// Block = 128 tokens, warp = head h. out[128x64] = (gk . v) @ Wr^T + q.
// Wr in smem (fp16, ldmatrix); A-frags built from gmem v (fp16) * gk.
// ---------------------------------------------------------------------------
#define WR_ROWB 144

__global__ __launch_bounds__(256) void epilogue_mma(
    const float* __restrict__ Wr,
    float* __restrict__ out)
{
    __shared__ __align__(16) char wrs[64 * WR_ROWB];
    const int tid  = threadIdx.x;
    const int h    = tid >> 5;       // warp = head
    const int lane = tid & 31;
    const uint32_t sb = smem_u32(wrs);

    // Wr (fp32 row-major [j][i]) -> fp16 smem rows j, cols i
    for (int idx = tid; idx < 64 * 32; idx += 256) {
        int j  = idx >> 5;
        int ip = idx & 31;
        float2 w = *(const float2*)&Wr[j * 64 + ip * 2];
        *(__half2*)&wrs[j * WR_ROWB + ip * 4] = __floats2half2_rn(w.x, w.y);
    }
    __syncthreads();

    // B fragments: b[ks][nf][2], covering n=64, k=64
    uint32_t b[4][8][2];
    #pragma unroll
    for (int ks = 0; ks < 4; ks++) {
        #pragma unroll
        for (int nq = 0; nq < 4; nq++) {
            uint32_t row = (uint32_t)(nq * 16 + (lane & 7) + ((lane >> 4) << 3));
            uint32_t addr = sb + row * WR_ROWB + ks * 32 + (((lane >> 3) & 1) << 4);
            uint32_t t[4];
            LDSM4(t, addr);
            b[ks][nq * 2][0]     = t[0]; b[ks][nq * 2][1]     = t[1];
            b[ks][nq * 2 + 1][0] = t[2]; b[ks][nq * 2 + 1][1] = t[3];
        }
    }

    const int t0  = blockIdx.x * 128;
    const int bsh = ((t0 >> 8) << 3) + h;
    const int r   = lane >> 2;
    const int c2  = (lane & 3) * 2;

    // gk as half2 per (ks, half-k): cols ks*16+c2(+1) and +8
    uint32_t gkh[4][2];
    const float* gk = &g_gk[bsh * DH];
    #pragma unroll
    for (int ks = 0; ks < 4; ks++) {
        int col = ks * 16 + c2;
        gkh[ks][0] = h2u(__floats2half2_rn(gk[col],     gk[col + 1]));
        gkh[ks][1] = h2u(__floats2half2_rn(gk[col + 8], gk[col + 9]));
    }

    #pragma unroll
    for (int m = 0; m < 8; m++) {
        const int row0 = t0 + m * 16 + r;
        const size_t v0 = (size_t)row0 * DIMF + h * DH;
        const size_t v1 = v0 + (size_t)8 * DIMF;

        float acc[8][4];
        #pragma unroll
        for (int nf = 0; nf < 8; nf++)
            #pragma unroll
            for (int c = 0; c < 4; c++) acc[nf][c] = 0.f;

        #pragma unroll
        for (int ks = 0; ks < 4; ks++) {
            const int kc = ks * 16 + c2;
            __half2 x0 = *(const __half2*)&g_vh[v0 + kc];
            __half2 x1 = *(const __half2*)&g_vh[v1 + kc];
            __half2 x2 = *(const __half2*)&g_vh[v0 + kc + 8];
            __half2 x3 = *(const __half2*)&g_vh[v1 + kc + 8];
            uint32_t a[4];
            a[0] = h2u(__hmul2(x0, *(__half2*)&gkh[ks][0]));
            a[1] = h2u(__hmul2(x1, *(__half2*)&gkh[ks][0]));
            a[2] = h2u(__hmul2(x2, *(__half2*)&gkh[ks][1]));
            a[3] = h2u(__hmul2(x3, *(__half2*)&gkh[ks][1]));
            #pragma unroll
            for (int nf = 0; nf < 8; nf++)
                MMA16816F(acc[nf], a, b[ks][nf]);
        }

        #pragma unroll
        for (int nf = 0; nf < 8; nf++) {
            const size_t o0 = (size_t)row0 * DIMF + h * DH + nf * 8 + c2;
            const size_t o1 = o0 + (size_t)8 * DIMF;
            float2 q0 = *(const float2*)&g_q[o0];
            float2 q1 = *(const float2*)&g_q[o1];
            *(float2*)&out[o0] = make_float2(acc[nf][0] + q0.x, acc[nf][1] + q0.y);
            *(float2*)&out[o1] = make_float2(acc[nf][2] + q1.x, acc[nf][3] + q1.y);
        }
    }
}

// ---------------------------------------------------------------------------
extern "C" void kernel_launch(void* const* d_in, const int* in_sizes, int n_in,
                              void* d_out, int out_size)
{
    const float* x       = (const float*)d_in[0];
    const float* Wq      = (const float*)d_in[1];
    const float* Wk      = (const float*)d_in[2];
    const float* Wv      = (const float*)d_in[3];
    const float* Wr      = (const float*)d_in[4];
    const float* w_alpha = (const float*)d_in[5];
    const float* w_beta  = (const float*)d_in[6];
    float* out = (float*)d_out;

    static int smem_set = 0;
    if (!smem_set) {
        cudaFuncSetAttribute(gemm_qkv,
                             cudaFuncAttributeMaxDynamicSharedMemorySize, SMEMB);
        smem_set = 1;
    }

    cvt_x<<<32768, 256>>>(x);
    cvt_w<<<768, 256>>>(Wq, Wk, Wv);

    dim3 g1(T_TOK / 128, DIMF / 128, 3);
    gemm_qkv<<<g1, 256, SMEMB>>>();

    global_qk<<<BSCNT * NHEADS, 256>>>(w_alpha, w_beta);

    epilogue_mma<<<T_TOK / 128, 256>>>(Wr, out);
}

// round 15
// speedup vs baseline: 1.8794x; 1.1054x over previous
#include <cuda_runtime.h>
#include <cuda_bf16.h>
#include <cuda_fp16.h>
#include <stdint.h>

// Problem constants
#define T_TOK   65536          // B*S*N tokens
#define DIMF    512
#define NHEADS  8
#define DH      64
#define N_PER   256
#define BSCNT   256
#define SCALE_F 0.044194173824159216f   // 512^-0.5

// Scratch (device globals: allocation-free per harness rules)
__device__ __half g_qh[(size_t)T_TOK * DIMF];
__device__ __half g_kh[(size_t)T_TOK * DIMF];
__device__ __half g_vh[(size_t)T_TOK * DIMF];
__device__ float g_gk[BSCNT * NHEADS * DH];
__device__ __half g_xh[(size_t)T_TOK * DIMF];
__device__ __half g_wh[3 * DIMF * DIMF];

// ---------------------------------------------------------------------------
// PTX helpers
// ---------------------------------------------------------------------------
__device__ __forceinline__ uint32_t smem_u32(const void* p) {
    uint32_t a;
    asm("{ .reg .u64 t; cvta.to.shared.u64 t, %1; cvt.u32.u64 %0, t; }" : "=r"(a) : "l"(p));
    return a;
}
#define CP16(s, g) asm volatile("cp.async.cg.shared.global [%0], [%1], 16;" :: "r"(s), "l"(g))
#define CP_COMMIT() asm volatile("cp.async.commit_group;")
#define CP_WAITG(n) asm volatile("cp.async.wait_group %0;" :: "n"(n))

#define LDSM4(r, a) \
    asm volatile("ldmatrix.sync.aligned.m8n8.x4.shared.b16 {%0,%1,%2,%3}, [%4];" \
        : "=r"((r)[0]), "=r"((r)[1]), "=r"((r)[2]), "=r"((r)[3]) : "r"(a))

#define MMA16816F(d, a, b) \
    asm volatile("mma.sync.aligned.m16n8k16.row.col.f32.f16.f16.f32 " \
        "{%0,%1,%2,%3}, {%4,%5,%6,%7}, {%8,%9}, {%0,%1,%2,%3};" \
        : "+f"((d)[0]), "+f"((d)[1]), "+f"((d)[2]), "+f"((d)[3]) \
        : "r"((a)[0]), "r"((a)[1]), "r"((a)[2]), "r"((a)[3]), "r"((b)[0]), "r"((b)[1]))

__device__ __forceinline__ uint32_t h2u(__half2 h) {
    uint32_t u; asm("mov.b32 %0, %1;" : "=r"(u) : "r"(*(uint32_t*)&h)); return u;
}

// ---------------------------------------------------------------------------
// Kernel 0a: x (fp32) -> fp16
// ---------------------------------------------------------------------------
__global__ __launch_bounds__(256) void cvt_x(const float* __restrict__ x)
{
    size_t i = ((size_t)blockIdx.x * 256 + threadIdx.x) * 4;
    float4 v = *(const float4*)(x + i);
    __half2* ph = (__half2*)&g_xh[i];
    ph[0] = __floats2half2_rn(v.x, v.y);
    ph[1] = __floats2half2_rn(v.z, v.w);
}

// ---------------------------------------------------------------------------
// Kernel 0b: Wq/Wk/Wv -> fp16 (concatenated [3][512*512])
// ---------------------------------------------------------------------------
__global__ __launch_bounds__(256) void cvt_w(const float* __restrict__ Wq,
                                             const float* __restrict__ Wk,
                                             const float* __restrict__ Wv)
{
    size_t e = ((size_t)blockIdx.x * 256 + threadIdx.x) * 4;   // < 786432
    int z = (int)(e >> 18);
    size_t off = e & 262143;
    const float* W = (z == 0) ? Wq : (z == 1 ? Wk : Wv);
    float4 v = *(const float4*)(W + off);
    __half2* ph = (__half2*)&g_wh[e];
    ph[0] = __floats2half2_rn(v.x, v.y);
    ph[1] = __floats2half2_rn(v.z, v.w);
}

// ---------------------------------------------------------------------------
// Fused QKV GEMM (fp16): CTA tile 128x256, BK=32, 8 warps 2x4,
// warp tile 64x64, 3-stage cp.async pipeline. fp16 output for q/k/v.
// blockIdx.z selects W slice + output.
// ---------------------------------------------------------------------------
#define ROWB    80
#define ATB     (128 * ROWB)        // 10240
#define BTB     (256 * ROWB)        // 20480
#define STAGEB  (ATB + BTB)         // 30720
#define NST     3
#define SMEMB   (NST * STAGEB)      // 92160

__global__ __launch_bounds__(256, 1) void gemm_qkv()
{
    extern __shared__ char smc[];
    const uint32_t sb = smem_u32(smc);
    const int tid  = threadIdx.x;
    const int wid  = tid >> 5;
    const int lane = tid & 31;
    const int it  = blockIdx.x * 128;
    const int jtb = blockIdx.y * 256;
    const int z   = blockIdx.z;

    const __half* xh = g_xh;
    const __half* wh = g_wh + (size_t)z * DIMF * DIMF;
    __half* out = (z == 0) ? g_qh : (z == 1 ? g_kh : g_vh);

    const int wm = (wid >> 2) * 64;   // 0 or 64
    const int wn = (wid & 3) * 64;    // 0,64,128,192

    float acc[4][8][4];
    #pragma unroll
    for (int a = 0; a < 4; a++)
        #pragma unroll
        for (int b = 0; b < 8; b++)
            #pragma unroll
            for (int c = 0; c < 4; c++) acc[a][b][c] = 0.f;

    const int lr = tid >> 2;      // 0..63
    const int lc = tid & 3;       // 16B chunk col

#define ISSUE(buf, k0) do { \
    uint32_t base = sb + (uint32_t)(buf) * STAGEB; \
    uint32_t sA = base + lr * ROWB + lc * 16; \
    CP16(sA,             xh + (size_t)(it + lr)      * DIMF + (k0) + lc * 8); \
    CP16(sA + 64 * ROWB, xh + (size_t)(it + lr + 64) * DIMF + (k0) + lc * 8); \
    uint32_t sB = base + ATB + lr * ROWB + lc * 16; \
    CP16(sB,              wh + (size_t)(jtb + lr)       * DIMF + (k0) + lc * 8); \
    CP16(sB +  64 * ROWB, wh + (size_t)(jtb + lr +  64) * DIMF + (k0) + lc * 8); \
    CP16(sB + 128 * ROWB, wh + (size_t)(jtb + lr + 128) * DIMF + (k0) + lc * 8); \
    CP16(sB + 192 * ROWB, wh + (size_t)(jtb + lr + 192) * DIMF + (k0) + lc * 8); \
} while (0)

    ISSUE(0, 0);  CP_COMMIT();
    ISSUE(1, 32); CP_COMMIT();

    #pragma unroll 1
    for (int i = 0; i < 16; i++) {
        CP_WAITG(NST - 2);
        __syncthreads();
        const int nk = i + NST - 1;
        if (nk < 16) ISSUE(nk % NST, nk * 32);
        CP_COMMIT();

        const uint32_t b0 = sb + (uint32_t)(i % NST) * STAGEB;
        #pragma unroll
        for (int ks = 0; ks < 2; ks++) {
            const int kb = ks * 32;
            uint32_t ah[4][4], bh[8][2];
            #pragma unroll
            for (int mf = 0; mf < 4; mf++) {
                uint32_t addr = b0 + (uint32_t)(wm + mf * 16 + (lane & 15)) * ROWB
                              + kb + ((lane >> 4) << 4);
                LDSM4(ah[mf], addr);
            }
            #pragma unroll
            for (int nq = 0; nq < 4; nq++) {
                uint32_t row = (uint32_t)(wn + nq * 16 + (lane & 7) + ((lane >> 4) << 3));
                uint32_t addr = b0 + ATB + row * ROWB + kb + (((lane >> 3) & 1) << 4);
                uint32_t t[4];
                LDSM4(t, addr);
                bh[nq * 2][0]     = t[0]; bh[nq * 2][1]     = t[1];
                bh[nq * 2 + 1][0] = t[2]; bh[nq * 2 + 1][1] = t[3];
            }
            #pragma unroll
            for (int mf = 0; mf < 4; mf++)
                #pragma unroll
                for (int nf = 0; nf < 8; nf++)
                    MMA16816F(acc[mf][nf], ah[mf], bh[nf]);
        }
    }
#undef ISSUE

    #pragma unroll
    for (int mf = 0; mf < 4; mf++) {
        const int row = it + wm + mf * 16 + (lane >> 2);
        #pragma unroll
        for (int nf = 0; nf < 8; nf++) {
            const int col = jtb + wn + nf * 8 + (lane & 3) * 2;
            *(__half2*)&out[(size_t)row * DIMF + col] =
                __floats2half2_rn(acc[mf][nf][0], acc[mf][nf][1]);
            *(__half2*)&out[(size_t)(row + 8) * DIMF + col] =
                __floats2half2_rn(acc[mf][nf][2], acc[mf][nf][3]);
        }
    }
}

// ---------------------------------------------------------------------------
// Kernel 2: per (b,s,h): global_query then global_key.
// 8-lane row-groups: thread owns 8 d-values; 3-shfl reduce; 4 rows/warp ILP.
// q, k read as fp16. No max-subtraction (logits tiny).
// ---------------------------------------------------------------------------
__global__ __launch_bounds__(256) void global_qk(
    const float* __restrict__ w_alpha,
    const float* __restrict__ w_beta)
{
    const int bsh = blockIdx.x;            // 0..2047
    const int bs  = bsh >> 3;
    const int h   = bsh & 7;
    const size_t base = ((size_t)bs * N_PER) * DIMF + (size_t)h * DH;

    const int tid  = threadIdx.x;
    const int warp = tid >> 5;
    const int lane = tid & 31;
    const int li   = lane & 7;       // octet position
    const int sub  = lane >> 3;      // 0..3 row within warp group
    const int d0   = li * 8;

    __shared__ float s_red[8][64];
    __shared__ float s_gq[64];

    // ---- pass 1: global_query from q (fp16) ----
    float wa[8];
    *(float4*)&wa[0] = *(const float4*)&w_alpha[d0];
    *(float4*)&wa[4] = *(const float4*)&w_alpha[d0 + 4];
    #pragma unroll
    for (int j = 0; j < 8; j++) wa[j] *= SCALE_F;

    float acc[8];
    #pragma unroll
    for (int j = 0; j < 8; j++) acc[j] = 0.f;

    for (int n = warp * 4 + sub; n < N_PER; n += 32) {
        uint4 raw = *(const uint4*)&g_qh[base + (size_t)n * DIMF + d0];
        const __half2* hp = (const __half2*)&raw;
        float qv[8];
        #pragma unroll
        for (int jj = 0; jj < 4; jj++) {
            float2 f = __half22float2(hp[jj]);
            qv[2 * jj] = f.x; qv[2 * jj + 1] = f.y;
        }
        float e[8], s = 0.f;
        #pragma unroll
        for (int j = 0; j < 8; j++) { e[j] = __expf(qv[j] * wa[j]); s += e[j]; }
        s += __shfl_xor_sync(~0u, s, 1);
        s += __shfl_xor_sync(~0u, s, 2);
        s += __shfl_xor_sync(~0u, s, 4);
        const float inv = 1.f / s;
        #pragma unroll
        for (int j = 0; j < 8; j++) acc[j] += qv[j] * e[j] * inv;
    }
    #pragma unroll
    for (int j = 0; j < 8; j++) {
        acc[j] += __shfl_xor_sync(~0u, acc[j], 8);
        acc[j] += __shfl_xor_sync(~0u, acc[j], 16);
    }
    if (sub == 0) {
        *(float4*)&s_red[warp][d0]     = make_float4(acc[0], acc[1], acc[2], acc[3]);
        *(float4*)&s_red[warp][d0 + 4] = make_float4(acc[4], acc[5], acc[6], acc[7]);
    }
    __syncthreads();
    if (tid < 64) {
        float s = 0.f;
        #pragma unroll
        for (int w = 0; w < 8; w++) s += s_red[w][tid];
        s_gq[tid] = s;
    }
    __syncthreads();

    // ---- pass 2: global_key from p = gq * k (fp16 k) ----
    float wb[8], gq[8];
    *(float4*)&wb[0] = *(const float4*)&w_beta[d0];
    *(float4*)&wb[4] = *(const float4*)&w_beta[d0 + 4];
    #pragma unroll
    for (int j = 0; j < 8; j++) wb[j] *= SCALE_F;
    *(float4*)&gq[0] = *(const float4*)&s_gq[d0];
    *(float4*)&gq[4] = *(const float4*)&s_gq[d0 + 4];

    #pragma unroll
    for (int j = 0; j < 8; j++) acc[j] = 0.f;

    for (int n = warp * 4 + sub; n < N_PER; n += 32) {
        uint4 raw = *(const uint4*)&g_kh[base + (size_t)n * DIMF + d0];
        const __half2* hp = (const __half2*)&raw;
        float p[8];
        #pragma unroll
        for (int jj = 0; jj < 4; jj++) {
            float2 f = __half22float2(hp[jj]);
            p[2 * jj] = gq[2 * jj] * f.x; p[2 * jj + 1] = gq[2 * jj + 1] * f.y;
        }
        float e[8], s = 0.f;
        #pragma unroll
        for (int j = 0; j < 8; j++) { e[j] = __expf(p[j] * wb[j]); s += e[j]; }
        s += __shfl_xor_sync(~0u, s, 1);
        s += __shfl_xor_sync(~0u, s, 2);
        s += __shfl_xor_sync(~0u, s, 4);
        const float inv = 1.f / s;
        #pragma unroll
        for (int j = 0; j < 8; j++) acc[j] += p[j] * e[j] * inv;
    }
    #pragma unroll
    for (int j = 0; j < 8; j++) {
        acc[j] += __shfl_xor_sync(~0u, acc[j], 8);
        acc[j] += __shfl_xor_sync(~0u, acc[j], 16);
    }
    __syncthreads();
    if (sub == 0) {
        *(float4*)&s_red[warp][d0]     = make_float4(acc[0], acc[1], acc[2], acc[3]);
        *(float4*)&s_red[warp][d0 + 4] = make_float4(acc[4], acc[5], acc[6], acc[7]);
    }
    __syncthreads();
    if (tid < 64) {
        float s = 0.f;
        #pragma unroll
        for (int w = 0; w < 8; w++) s += s_red[w][tid];
        g_gk[bsh * DH + tid] = s;
    }
}

// ---------------------------------------------------------------------------
// Kernel 3: tensor-core epilogue.
// Block = 128 tokens, warp = head h. out[128x64] = (gk . v) @ Wr^T + q.
// ---------------------------------------------------------------------------
#define WR_ROWB 144

__global__ __launch_bounds__(256) void epilogue_mma(
    const float* __restrict__ Wr,
    float* __restrict__ out)
{
    __shared__ __align__(16) char wrs[64 * WR_ROWB];
    const int tid  = threadIdx.x;
    const int h    = tid >> 5;       // warp = head
    const int lane = tid & 31;
    const uint32_t sb = smem_u32(wrs);

    // Wr (fp32 row-major [j][i]) -> fp16 smem rows j, cols i
    for (int idx = tid; idx < 64 * 32; idx += 256) {
        int j  = idx >> 5;
        int ip = idx & 31;
        float2 w = *(const float2*)&Wr[j * 64 + ip * 2];
        *(__half2*)&wrs[j * WR_ROWB + ip * 4] = __floats2half2_rn(w.x, w.y);
    }
    __syncthreads();

    // B fragments: b[ks][nf][2], covering n=64, k=64
    uint32_t b[4][8][2];
    #pragma unroll
    for (int ks = 0; ks < 4; ks++) {
        #pragma unroll
        for (int nq = 0; nq < 4; nq++) {
            uint32_t row = (uint32_t)(nq * 16 + (lane & 7) + ((lane >> 4) << 3));
            uint32_t addr = sb + row * WR_ROWB + ks * 32 + (((lane >> 3) & 1) << 4);
            uint32_t t[4];
            LDSM4(t, addr);
            b[ks][nq * 2][0]     = t[0]; b[ks][nq * 2][1]     = t[1];
            b[ks][nq * 2 + 1][0] = t[2]; b[ks][nq * 2 + 1][1] = t[3];
        }
    }

    const int t0  = blockIdx.x * 128;
    const int bsh = ((t0 >> 8) << 3) + h;
    const int r   = lane >> 2;
    const int c2  = (lane & 3) * 2;

    // gk as half2 per (ks, half-k)
    uint32_t gkh[4][2];
    const float* gk = &g_gk[bsh * DH];
    #pragma unroll
    for (int ks = 0; ks < 4; ks++) {
        int col = ks * 16 + c2;
        gkh[ks][0] = h2u(__floats2half2_rn(gk[col],     gk[col + 1]));
        gkh[ks][1] = h2u(__floats2half2_rn(gk[col + 8], gk[col + 9]));
    }

    #pragma unroll
    for (int m = 0; m < 8; m++) {
        const int row0 = t0 + m * 16 + r;
        const size_t v0 = (size_t)row0 * DIMF + h * DH;
        const size_t v1 = v0 + (size_t)8 * DIMF;

        float acc[8][4];
        #pragma unroll
        for (int nf = 0; nf < 8; nf++)
            #pragma unroll
            for (int c = 0; c < 4; c++) acc[nf][c] = 0.f;

        #pragma unroll
        for (int ks = 0; ks < 4; ks++) {
            const int kc = ks * 16 + c2;
            __half2 x0 = *(const __half2*)&g_vh[v0 + kc];
            __half2 x1 = *(const __half2*)&g_vh[v1 + kc];
            __half2 x2 = *(const __half2*)&g_vh[v0 + kc + 8];
            __half2 x3 = *(const __half2*)&g_vh[v1 + kc + 8];
            uint32_t a[4];
            a[0] = h2u(__hmul2(x0, *(__half2*)&gkh[ks][0]));
            a[1] = h2u(__hmul2(x1, *(__half2*)&gkh[ks][0]));
            a[2] = h2u(__hmul2(x2, *(__half2*)&gkh[ks][1]));
            a[3] = h2u(__hmul2(x3, *(__half2*)&gkh[ks][1]));
            #pragma unroll
            for (int nf = 0; nf < 8; nf++)
                MMA16816F(acc[nf], a, b[ks][nf]);
        }

        #pragma unroll
        for (int nf = 0; nf < 8; nf++) {
            const size_t o0 = (size_t)row0 * DIMF + h * DH + nf * 8 + c2;
            const size_t o1 = o0 + (size_t)8 * DIMF;
            float2 q0 = __half22float2(*(const __half2*)&g_qh[o0]);
            float2 q1 = __half22float2(*(const __half2*)&g_qh[o1]);
            *(float2*)&out[o0] = make_float2(acc[nf][0] + q0.x, acc[nf][1] + q0.y);
            *(float2*)&out[o1] = make_float2(acc[nf][2] + q1.x, acc[nf][3] + q1.y);
        }
    }
}

// ---------------------------------------------------------------------------
extern "C" void kernel_launch(void* const* d_in, const int* in_sizes, int n_in,
                              void* d_out, int out_size)
{
    const float* x       = (const float*)d_in[0];
    const float* Wq      = (const float*)d_in[1];
    const float* Wk      = (const float*)d_in[2];
    const float* Wv      = (const float*)d_in[3];
    const float* Wr      = (const float*)d_in[4];
    const float* w_alpha = (const float*)d_in[5];
    const float* w_beta  = (const float*)d_in[6];
    float* out = (float*)d_out;

    static int smem_set = 0;
    if (!smem_set) {
        cudaFuncSetAttribute(gemm_qkv,
                             cudaFuncAttributeMaxDynamicSharedMemorySize, SMEMB);
        smem_set = 1;
    }

    cvt_x<<<32768, 256>>>(x);
    cvt_w<<<768, 256>>>(Wq, Wk, Wv);

    dim3 g1(T_TOK / 128, DIMF / 256, 3);   // 512 x 2 x 3
    gemm_qkv<<<g1, 256, SMEMB>>>();

    global_qk<<<BSCNT * NHEADS, 256>>>(w_alpha, w_beta);

    epilogue_mma<<<T_TOK / 128, 256>>>(Wr, out);
}

// round 17
// speedup vs baseline: 1.8805x; 1.0006x over previous
#include <cuda_runtime.h>
#include <cuda_bf16.h>
#include <cuda_fp16.h>
#include <stdint.h>

// Problem constants
#define T_TOK   65536          // B*S*N tokens
#define DIMF    512
#define NHEADS  8
#define DH      64
#define N_PER   256
#define BSCNT   256
#define SCALE_F 0.044194173824159216f   // 512^-0.5

// Scratch (device globals: allocation-free per harness rules)
__device__ __half g_qh[(size_t)T_TOK * DIMF];
__device__ __half g_kh[(size_t)T_TOK * DIMF];
__device__ __half g_vh[(size_t)T_TOK * DIMF];
__device__ float g_gk[BSCNT * NHEADS * DH];
__device__ __half g_xh[(size_t)T_TOK * DIMF];
__device__ __half g_wh[3 * DIMF * DIMF];

// ---------------------------------------------------------------------------
// PTX helpers
// ---------------------------------------------------------------------------
__device__ __forceinline__ uint32_t smem_u32(const void* p) {
    uint32_t a;
    asm("{ .reg .u64 t; cvta.to.shared.u64 t, %1; cvt.u32.u64 %0, t; }" : "=r"(a) : "l"(p));
    return a;
}
#define CP16(s, g) asm volatile("cp.async.cg.shared.global [%0], [%1], 16;" :: "r"(s), "l"(g))
#define CP_COMMIT() asm volatile("cp.async.commit_group;")
#define CP_WAITG(n) asm volatile("cp.async.wait_group %0;" :: "n"(n))

#define LDSM4(r, a) \
    asm volatile("ldmatrix.sync.aligned.m8n8.x4.shared.b16 {%0,%1,%2,%3}, [%4];" \
        : "=r"((r)[0]), "=r"((r)[1]), "=r"((r)[2]), "=r"((r)[3]) : "r"(a))

#define MMA16816F(d, a, b) \
    asm volatile("mma.sync.aligned.m16n8k16.row.col.f32.f16.f16.f32 " \
        "{%0,%1,%2,%3}, {%4,%5,%6,%7}, {%8,%9}, {%0,%1,%2,%3};" \
        : "+f"((d)[0]), "+f"((d)[1]), "+f"((d)[2]), "+f"((d)[3]) \
        : "r"((a)[0]), "r"((a)[1]), "r"((a)[2]), "r"((a)[3]), "r"((b)[0]), "r"((b)[1]))

__device__ __forceinline__ uint32_t h2u(__half2 h) {
    uint32_t u; asm("mov.b32 %0, %1;" : "=r"(u) : "r"(*(uint32_t*)&h)); return u;
}
__device__ __forceinline__ uint32_t hmul2u(uint32_t a, uint32_t b) {
    __half2 r = __hmul2(*(__half2*)&a, *(__half2*)&b);
    return *(uint32_t*)&r;
}

// ---------------------------------------------------------------------------
// Kernel 0a: x (fp32) -> fp16
// ---------------------------------------------------------------------------
__global__ __launch_bounds__(256) void cvt_x(const float* __restrict__ x)
{
    size_t i = ((size_t)blockIdx.x * 256 + threadIdx.x) * 4;
    float4 v = *(const float4*)(x + i);
    __half2* ph = (__half2*)&g_xh[i];
    ph[0] = __floats2half2_rn(v.x, v.y);
    ph[1] = __floats2half2_rn(v.z, v.w);
}

// ---------------------------------------------------------------------------
// Kernel 0b: Wq/Wk/Wv -> fp16 (concatenated [3][512*512])
// ---------------------------------------------------------------------------
__global__ __launch_bounds__(256) void cvt_w(const float* __restrict__ Wq,
                                             const float* __restrict__ Wk,
                                             const float* __restrict__ Wv)
{
    size_t e = ((size_t)blockIdx.x * 256 + threadIdx.x) * 4;   // < 786432
    int z = (int)(e >> 18);
    size_t off = e & 262143;
    const float* W = (z == 0) ? Wq : (z == 1 ? Wk : Wv);
    float4 v = *(const float4*)(W + off);
    __half2* ph = (__half2*)&g_wh[e];
    ph[0] = __floats2half2_rn(v.x, v.y);
    ph[1] = __floats2half2_rn(v.z, v.w);
}

// ---------------------------------------------------------------------------
// Fused QKV GEMM (fp16): CTA tile 128x256, BK=32, 8 warps 2x4,
// warp tile 64x64, 3-stage cp.async pipeline. fp16 output.
// z = blockIdx.z + zoff: 0 -> q, 1 -> k, 2 -> v.
// ---------------------------------------------------------------------------
#define ROWB    80
#define ATB     (128 * ROWB)        // 10240
#define BTB     (256 * ROWB)        // 20480
#define STAGEB  (ATB + BTB)         // 30720
#define NST     3
#define SMEMB   (NST * STAGEB)      // 92160

__global__ __launch_bounds__(256, 1) void gemm_qkv(int zoff)
{
    extern __shared__ char smc[];
    const uint32_t sb = smem_u32(smc);
    const int tid  = threadIdx.x;
    const int wid  = tid >> 5;
    const int lane = tid & 31;
    const int it  = blockIdx.x * 128;
    const int jtb = blockIdx.y * 256;
    const int z   = blockIdx.z + zoff;

    const __half* xh = g_xh;
    const __half* wh = g_wh + (size_t)z * DIMF * DIMF;
    __half* out = (z == 0) ? g_qh : (z == 1 ? g_kh : g_vh);

    const int wm = (wid >> 2) * 64;   // 0 or 64
    const int wn = (wid & 3) * 64;    // 0,64,128,192

    float acc[4][8][4];
    #pragma unroll
    for (int a = 0; a < 4; a++)
        #pragma unroll
        for (int b = 0; b < 8; b++)
            #pragma unroll
            for (int c = 0; c < 4; c++) acc[a][b][c] = 0.f;

    const int lr = tid >> 2;      // 0..63
    const int lc = tid & 3;       // 16B chunk col

#define ISSUE(buf, k0) do { \
    uint32_t base = sb + (uint32_t)(buf) * STAGEB; \
    uint32_t sA = base + lr * ROWB + lc * 16; \
    CP16(sA,             xh + (size_t)(it + lr)      * DIMF + (k0) + lc * 8); \
    CP16(sA + 64 * ROWB, xh + (size_t)(it + lr + 64) * DIMF + (k0) + lc * 8); \
    uint32_t sB = base + ATB + lr * ROWB + lc * 16; \
    CP16(sB,              wh + (size_t)(jtb + lr)       * DIMF + (k0) + lc * 8); \
    CP16(sB +  64 * ROWB, wh + (size_t)(jtb + lr +  64) * DIMF + (k0) + lc * 8); \
    CP16(sB + 128 * ROWB, wh + (size_t)(jtb + lr + 128) * DIMF + (k0) + lc * 8); \
    CP16(sB + 192 * ROWB, wh + (size_t)(jtb + lr + 192) * DIMF + (k0) + lc * 8); \
} while (0)

    ISSUE(0, 0);  CP_COMMIT();
    ISSUE(1, 32); CP_COMMIT();

    #pragma unroll 1
    for (int i = 0; i < 16; i++) {
        CP_WAITG(NST - 2);
        __syncthreads();
        const int nk = i + NST - 1;
        if (nk < 16) ISSUE(nk % NST, nk * 32);
        CP_COMMIT();

        const uint32_t b0 = sb + (uint32_t)(i % NST) * STAGEB;
        #pragma unroll
        for (int ks = 0; ks < 2; ks++) {
            const int kb = ks * 32;
            uint32_t ah[4][4], bh[8][2];
            #pragma unroll
            for (int mf = 0; mf < 4; mf++) {
                uint32_t addr = b0 + (uint32_t)(wm + mf * 16 + (lane & 15)) * ROWB
                              + kb + ((lane >> 4) << 4);
                LDSM4(ah[mf], addr);
            }
            #pragma unroll
            for (int nq = 0; nq < 4; nq++) {
                uint32_t row = (uint32_t)(wn + nq * 16 + (lane & 7) + ((lane >> 4) << 3));
                uint32_t addr = b0 + ATB + row * ROWB + kb + (((lane >> 3) & 1) << 4);
                uint32_t t[4];
                LDSM4(t, addr);
                bh[nq * 2][0]     = t[0]; bh[nq * 2][1]     = t[1];
                bh[nq * 2 + 1][0] = t[2]; bh[nq * 2 + 1][1] = t[3];
            }
            #pragma unroll
            for (int mf = 0; mf < 4; mf++)
                #pragma unroll
                for (int nf = 0; nf < 8; nf++)
                    MMA16816F(acc[mf][nf], ah[mf], bh[nf]);
        }
    }
#undef ISSUE

    #pragma unroll
    for (int mf = 0; mf < 4; mf++) {
        const int row = it + wm + mf * 16 + (lane >> 2);
        #pragma unroll
        for (int nf = 0; nf < 8; nf++) {
            const int col = jtb + wn + nf * 8 + (lane & 3) * 2;
            *(__half2*)&out[(size_t)row * DIMF + col] =
                __floats2half2_rn(acc[mf][nf][0], acc[mf][nf][1]);
            *(__half2*)&out[(size_t)(row + 8) * DIMF + col] =
                __floats2half2_rn(acc[mf][nf][2], acc[mf][nf][3]);
        }
    }
}

// ---------------------------------------------------------------------------
// Kernel 2: per (b,s,h): global_query then global_key (fp16 q,k).
// ---------------------------------------------------------------------------
__global__ __launch_bounds__(256) void global_qk(
    const float* __restrict__ w_alpha,
    const float* __restrict__ w_beta)
{
    const int bsh = blockIdx.x;            // 0..2047
    const int bs  = bsh >> 3;
    const int h   = bsh & 7;
    const size_t base = ((size_t)bs * N_PER) * DIMF + (size_t)h * DH;

    const int tid  = threadIdx.x;
    const int warp = tid >> 5;
    const int lane = tid & 31;
    const int li   = lane & 7;
    const int sub  = lane >> 3;
    const int d0   = li * 8;

    __shared__ float s_red[8][64];
    __shared__ float s_gq[64];

    float wa[8];
    *(float4*)&wa[0] = *(const float4*)&w_alpha[d0];
    *(float4*)&wa[4] = *(const float4*)&w_alpha[d0 + 4];
    #pragma unroll
    for (int j = 0; j < 8; j++) wa[j] *= SCALE_F;

    float acc[8];
    #pragma unroll
    for (int j = 0; j < 8; j++) acc[j] = 0.f;

    for (int n = warp * 4 + sub; n < N_PER; n += 32) {
        uint4 raw = *(const uint4*)&g_qh[base + (size_t)n * DIMF + d0];
        const __half2* hp = (const __half2*)&raw;
        float qv[8];
        #pragma unroll
        for (int jj = 0; jj < 4; jj++) {
            float2 f = __half22float2(hp[jj]);
            qv[2 * jj] = f.x; qv[2 * jj + 1] = f.y;
        }
        float e[8], s = 0.f;
        #pragma unroll
        for (int j = 0; j < 8; j++) { e[j] = __expf(qv[j] * wa[j]); s += e[j]; }
        s += __shfl_xor_sync(~0u, s, 1);
        s += __shfl_xor_sync(~0u, s, 2);
        s += __shfl_xor_sync(~0u, s, 4);
        const float inv = 1.f / s;
        #pragma unroll
        for (int j = 0; j < 8; j++) acc[j] += qv[j] * e[j] * inv;
    }
    #pragma unroll
    for (int j = 0; j < 8; j++) {
        acc[j] += __shfl_xor_sync(~0u, acc[j], 8);
        acc[j] += __shfl_xor_sync(~0u, acc[j], 16);
    }
    if (sub == 0) {
        *(float4*)&s_red[warp][d0]     = make_float4(acc[0], acc[1], acc[2], acc[3]);
        *(float4*)&s_red[warp][d0 + 4] = make_float4(acc[4], acc[5], acc[6], acc[7]);
    }
    __syncthreads();
    if (tid < 64) {
        float s = 0.f;
        #pragma unroll
        for (int w = 0; w < 8; w++) s += s_red[w][tid];
        s_gq[tid] = s;
    }
    __syncthreads();

    float wb[8], gq[8];
    *(float4*)&wb[0] = *(const float4*)&w_beta[d0];
    *(float4*)&wb[4] = *(const float4*)&w_beta[d0 + 4];
    #pragma unroll
    for (int j = 0; j < 8; j++) wb[j] *= SCALE_F;
    *(float4*)&gq[0] = *(const float4*)&s_gq[d0];
    *(float4*)&gq[4] = *(const float4*)&s_gq[d0 + 4];

    #pragma unroll
    for (int j = 0; j < 8; j++) acc[j] = 0.f;

    for (int n = warp * 4 + sub; n < N_PER; n += 32) {
        uint4 raw = *(const uint4*)&g_kh[base + (size_t)n * DIMF + d0];
        const __half2* hp = (const __half2*)&raw;
        float p[8];
        #pragma unroll
        for (int jj = 0; jj < 4; jj++) {
            float2 f = __half22float2(hp[jj]);
            p[2 * jj] = gq[2 * jj] * f.x; p[2 * jj + 1] = gq[2 * jj + 1] * f.y;
        }
        float e[8], s = 0.f;
        #pragma unroll
        for (int j = 0; j < 8; j++) { e[j] = __expf(p[j] * wb[j]); s += e[j]; }
        s += __shfl_xor_sync(~0u, s, 1);
        s += __shfl_xor_sync(~0u, s, 2);
        s += __shfl_xor_sync(~0u, s, 4);
        const float inv = 1.f / s;
        #pragma unroll
        for (int j = 0; j < 8; j++) acc[j] += p[j] * e[j] * inv;
    }
    #pragma unroll
    for (int j = 0; j < 8; j++) {
        acc[j] += __shfl_xor_sync(~0u, acc[j], 8);
        acc[j] += __shfl_xor_sync(~0u, acc[j], 16);
    }
    __syncthreads();
    if (sub == 0) {
        *(float4*)&s_red[warp][d0]     = make_float4(acc[0], acc[1], acc[2], acc[3]);
        *(float4*)&s_red[warp][d0 + 4] = make_float4(acc[4], acc[5], acc[6], acc[7]);
    }
    __syncthreads();
    if (tid < 64) {
        float s = 0.f;
        #pragma unroll
        for (int w = 0; w < 8; w++) s += s_red[w][tid];
        g_gk[bsh * DH + tid] = s;
    }
}

// ---------------------------------------------------------------------------
// Kernel 3: tensor-core epilogue v2.
// Block = 128 tokens, warp = head h. out[128x64] = v @ (Wr.gk)^T + q.
// gk folded into B frags once; v staged via cp.async (double buffer) + ldmatrix.
// ---------------------------------------------------------------------------
#define VSTR 144

__global__ __launch_bounds__(256) void epilogue_mma(
    const float* __restrict__ Wr,
    float* __restrict__ out)
{
    __shared__ __align__(16) char wrs[64 * VSTR];            // 9216
    __shared__ __align__(16) char vst[2][8][16 * VSTR];      // 36864
    const int tid  = threadIdx.x;
    const int h    = tid >> 5;       // warp = head
    const int lane = tid & 31;
    const uint32_t sbw = smem_u32(wrs);

    // Wr (fp32 row-major [j][i]) -> fp16 smem rows j, cols i
    for (int idx = tid; idx < 64 * 32; idx += 256) {
        int j  = idx >> 5;
        int ip = idx & 31;
        float2 w = *(const float2*)&Wr[j * 64 + ip * 2];
        *(__half2*)&wrs[j * VSTR + ip * 4] = __floats2half2_rn(w.x, w.y);
    }
    __syncthreads();

    const int t0  = blockIdx.x * 128;
    const int bsh = ((t0 >> 8) << 3) + h;
    const int r   = lane >> 2;
    const int c2  = (lane & 3) * 2;

    // gk as half2 per (ks, half-k)
    uint32_t gkh[4][2];
    const float* gk = &g_gk[bsh * DH];
    #pragma unroll
    for (int ks = 0; ks < 4; ks++) {
        int col = ks * 16 + c2;
        gkh[ks][0] = h2u(__floats2half2_rn(gk[col],     gk[col + 1]));
        gkh[ks][1] = h2u(__floats2half2_rn(gk[col + 8], gk[col + 9]));
    }

    // B fragments premultiplied by gk: b[ks][nf][2]
    uint32_t b[4][8][2];
    #pragma unroll
    for (int ks = 0; ks < 4; ks++) {
        #pragma unroll
        for (int nq = 0; nq < 4; nq++) {
            uint32_t row = (uint32_t)(nq * 16 + (lane & 7) + ((lane >> 4) << 3));
            uint32_t addr = sbw + row * VSTR + ks * 32 + (((lane >> 3) & 1) << 4);
            uint32_t t[4];
            LDSM4(t, addr);
            b[ks][nq * 2][0]     = hmul2u(t[0], gkh[ks][0]);
            b[ks][nq * 2][1]     = hmul2u(t[1], gkh[ks][1]);
            b[ks][nq * 2 + 1][0] = hmul2u(t[2], gkh[ks][0]);
            b[ks][nq * 2 + 1][1] = hmul2u(t[3], gkh[ks][1]);
        }
    }

    // v staging: per warp, 16 rows x 64 cols (128B) per m-iter
    const __half* vbase = g_vh + (size_t)t0 * DIMF + h * DH;
    const int srr = lane >> 1;            // staging row 0..15
    const int scb = (lane & 1) * 64;      // staging byte col 0/64
    const uint32_t vs0 = smem_u32(&vst[0][h][0]);
    const uint32_t vs1 = smem_u32(&vst[1][h][0]);

#define VISSUE(mm) do { \
    uint32_t dst = (((mm) & 1) ? vs1 : vs0) + srr * VSTR + scb; \
    const __half* src = vbase + (size_t)((mm) * 16 + srr) * DIMF + scb / 2; \
    CP16(dst,      src);      CP16(dst + 16, src + 8); \
    CP16(dst + 32, src + 16); CP16(dst + 48, src + 24); \
} while (0)

    VISSUE(0); CP_COMMIT();

    #pragma unroll 1
    for (int m = 0; m < 8; m++) {
        if (m < 7) { VISSUE(m + 1); CP_COMMIT(); CP_WAITG(1); }
        else       { CP_WAITG(0); }
        __syncthreads();

        const uint32_t vb = (m & 1) ? vs1 : vs0;
        uint32_t ah[4][4];
        #pragma unroll
        for (int ks = 0; ks < 4; ks++) {
            uint32_t addr = vb + (uint32_t)(lane & 15) * VSTR + ks * 32 + ((lane >> 4) << 4);
            LDSM4(ah[ks], addr);
        }

        float acc[8][4];
        #pragma unroll
        for (int nf = 0; nf < 8; nf++)
            #pragma unroll
            for (int c = 0; c < 4; c++) acc[nf][c] = 0.f;

        #pragma unroll
        for (int ks = 0; ks < 4; ks++)
            #pragma unroll
            for (int nf = 0; nf < 8; nf++)
                MMA16816F(acc[nf], ah[ks], b[ks][nf]);

        const int row0 = t0 + m * 16 + r;
        #pragma unroll
        for (int nf = 0; nf < 8; nf++) {
            const size_t o0 = (size_t)row0 * DIMF + h * DH + nf * 8 + c2;
            const size_t o1 = o0 + (size_t)8 * DIMF;
            float2 q0 = __half22float2(*(const __half2*)&g_qh[o0]);
            float2 q1 = __half22float2(*(const __half2*)&g_qh[o1]);
            *(float2*)&out[o0] = make_float2(acc[nf][0] + q0.x, acc[nf][1] + q0.y);
            *(float2*)&out[o1] = make_float2(acc[nf][2] + q1.x, acc[nf][3] + q1.y);
        }
    }
#undef VISSUE
}

// ---------------------------------------------------------------------------
extern "C" void kernel_launch(void* const* d_in, const int* in_sizes, int n_in,
                              void* d_out, int out_size)
{
    const float* x       = (const float*)d_in[0];
    const float* Wq      = (const float*)d_in[1];
    const float* Wk      = (const float*)d_in[2];
    const float* Wv      = (const float*)d_in[3];
    const float* Wr      = (const float*)d_in[4];
    const float* w_alpha = (const float*)d_in[5];
    const float* w_beta  = (const float*)d_in[6];
    float* out = (float*)d_out;

    static cudaStream_t s1 = nullptr;
    static cudaEvent_t evQK = nullptr, evV = nullptr;
    static int inited = 0;
    if (!inited) {
        cudaFuncSetAttribute(gemm_qkv,
                             cudaFuncAttributeMaxDynamicSharedMemorySize, SMEMB);
        cudaStreamCreateWithFlags(&s1, cudaStreamNonBlocking);
        cudaEventCreateWithFlags(&evQK, cudaEventDisableTiming);
        cudaEventCreateWithFlags(&evV, cudaEventDisableTiming);
        inited = 1;
    }

    // s0 (default stream): cvt, gemm q+k
    cvt_x<<<32768, 256>>>(x);
    cvt_w<<<768, 256>>>(Wq, Wk, Wv);

    dim3 gqk(T_TOK / 128, DIMF / 256, 2);   // z = 0,1 (q, k)
    gemm_qkv<<<gqk, 256, SMEMB>>>(0);
    cudaEventRecord(evQK, 0);

    // s1: gemm v, after gemm_qk (keeps q/k GEMM at full throughput,
    // then v GEMM overlaps with global_qk)
    cudaStreamWaitEvent(s1, evQK, 0);
    dim3 gv(T_TOK / 128, DIMF / 256, 1);    // z = 2 (v)
    gemm_qkv<<<gv, 256, SMEMB, s1>>>(2);
    cudaEventRecord(evV, s1);

    // s0: global_qk runs concurrently with gemm_v
    global_qk<<<BSCNT * NHEADS, 256>>>(w_alpha, w_beta);

    cudaStreamWaitEvent(0, evV, 0);
    epilogue_mma<<<T_TOK / 128, 256>>>(Wr, out);
}